// round 4
// baseline (speedup 1.0000x reference)
#include <cuda_runtime.h>
#include <cstdint>

#define NBODY      8192
#define BLOCK      128
#define NSPLIT     32
#define JCHUNK     (NBODY / NSPLIT)   // 256 bodies per block
#define NPAIRS     (JCHUNK / 2)       // 128 packed pairs
#define SOFT2      (0.01f * 0.01f)

__device__ __forceinline__ uint64_t f2_add(uint64_t a, uint64_t b) {
    uint64_t r; asm("add.rn.f32x2 %0, %1, %2;" : "=l"(r) : "l"(a), "l"(b)); return r;
}
__device__ __forceinline__ uint64_t f2_mul(uint64_t a, uint64_t b) {
    uint64_t r; asm("mul.rn.f32x2 %0, %1, %2;" : "=l"(r) : "l"(a), "l"(b)); return r;
}
__device__ __forceinline__ uint64_t f2_fma(uint64_t a, uint64_t b, uint64_t c) {
    uint64_t r; asm("fma.rn.f32x2 %0, %1, %2, %3;" : "=l"(r) : "l"(a), "l"(b), "l"(c)); return r;
}
__device__ __forceinline__ uint64_t f2_pack(float lo, float hi) {
    uint64_t r;
    asm("mov.b64 %0, {%1, %2};" : "=l"(r) : "f"(lo), "f"(hi));
    return r;
}
__device__ __forceinline__ void f2_unpack(float& lo, float& hi, uint64_t v) {
    asm("mov.b64 {%0, %1}, %2;" : "=f"(lo), "=f"(hi) : "l"(v));
}

__global__ void zero_out_kernel(float* out, int n) {
    int idx = blockIdx.x * blockDim.x + threadIdx.x;
    if (idx < n) out[idx] = 0.0f;
}

// 14 blocks/SM * 148 SMs = 2072 >= 2048 blocks -> single wave, no straggler.
__global__ __launch_bounds__(BLOCK, 14)
void nbody_kernel(const float* __restrict__ pos,
                  const float* __restrict__ mass,
                  float* __restrict__ out) {
    const int tid = threadIdx.x;
    const int i   = blockIdx.x * BLOCK + tid;

    const float xi = pos[3 * i + 0];
    const float yi = pos[3 * i + 1];
    const float zi = pos[3 * i + 2];

    // SoA shared tiles: each float2 holds bodies (2k, 2k+1) -> pre-packed f32x2
    __shared__ float2 shx[NPAIRS];
    __shared__ float2 shy[NPAIRS];
    __shared__ float2 shz[NPAIRS];
    __shared__ float2 shm[NPAIRS];

    if (tid < NPAIRS) {
        const int j = blockIdx.y * JCHUNK + 2 * tid;
        shx[tid] = make_float2(pos[3 * j + 0], pos[3 * j + 3]);
        shy[tid] = make_float2(pos[3 * j + 1], pos[3 * j + 4]);
        shz[tid] = make_float2(pos[3 * j + 2], pos[3 * j + 5]);
        shm[tid] = make_float2(mass[j], mass[j + 1]);
    }
    __syncthreads();

    const uint64_t nxi = f2_pack(-xi, -xi);
    const uint64_t nyi = f2_pack(-yi, -yi);
    const uint64_t nzi = f2_pack(-zi, -zi);
    const uint64_t s2p = f2_pack(SOFT2, SOFT2);

    uint64_t axp = 0ull, ayp = 0ull, azp = 0ull;   // packed (0.0f, 0.0f)

    const uint64_t* __restrict__ px = reinterpret_cast<const uint64_t*>(shx);
    const uint64_t* __restrict__ py = reinterpret_cast<const uint64_t*>(shy);
    const uint64_t* __restrict__ pz = reinterpret_cast<const uint64_t*>(shz);
    const uint64_t* __restrict__ pm = reinterpret_cast<const uint64_t*>(shm);

    #pragma unroll 8
    for (int k = 0; k < NPAIRS; k++) {
        const uint64_t xp = px[k];   // LDS.64, warp-broadcast
        const uint64_t yp = py[k];
        const uint64_t zp = pz[k];
        const uint64_t mp = pm[k];

        const uint64_t dx = f2_add(xp, nxi);
        const uint64_t dy = f2_add(yp, nyi);
        const uint64_t dz = f2_add(zp, nzi);

        uint64_t d2 = s2p;
        d2 = f2_fma(dx, dx, d2);
        d2 = f2_fma(dy, dy, d2);
        d2 = f2_fma(dz, dz, d2);

        float d0, d1;
        f2_unpack(d0, d1, d2);
        const float i0 = rsqrtf(d0);    // MUFU.RSQ
        const float i1 = rsqrtf(d1);
        const uint64_t invp = f2_pack(i0, i1);

        const uint64_t inv2  = f2_mul(invp, invp);
        const uint64_t minv2 = f2_mul(mp, inv2);
        const uint64_t w     = f2_mul(minv2, invp);   // m_j * d2^(-3/2)

        axp = f2_fma(w, dx, axp);
        ayp = f2_fma(w, dy, ayp);
        azp = f2_fma(w, dz, azp);
    }

    float axl, axh, ayl, ayh, azl, azh;
    f2_unpack(axl, axh, axp);
    f2_unpack(ayl, ayh, ayp);
    f2_unpack(azl, azh, azp);

    atomicAdd(&out[3 * i + 0], axl + axh);
    atomicAdd(&out[3 * i + 1], ayl + ayh);
    atomicAdd(&out[3 * i + 2], azl + azh);
}

extern "C" void kernel_launch(void* const* d_in, const int* in_sizes, int n_in,
                              void* d_out, int out_size) {
    const float* pos  = (const float*)d_in[0];   // (8192, 3) float32
    const float* mass = (const float*)d_in[1];   // (8192,)   float32
    float* out        = (float*)d_out;           // (8192, 3) float32

    zero_out_kernel<<<(NBODY * 3 + 255) / 256, 256>>>(out, NBODY * 3);

    dim3 grid(NBODY / BLOCK, NSPLIT);
    nbody_kernel<<<grid, BLOCK>>>(pos, mass, out);
}

// round 5
// speedup vs baseline: 1.1115x; 1.1115x over previous
#include <cuda_runtime.h>
#include <cstdint>

#define NBODY      8192
#define BLOCK      128
#define IT         2                      // i-bodies per thread
#define IBLK       (BLOCK * IT)           // 256 i-bodies per block
#define NSPLIT     32
#define JCHUNK     (NBODY / NSPLIT)       // 256 j-bodies per block
#define NPAIRS     (JCHUNK / 2)           // 128 packed j-pairs
#define SOFT2      (0.01f * 0.01f)

__device__ __forceinline__ uint64_t f2_add(uint64_t a, uint64_t b) {
    uint64_t r; asm("add.rn.f32x2 %0, %1, %2;" : "=l"(r) : "l"(a), "l"(b)); return r;
}
__device__ __forceinline__ uint64_t f2_mul(uint64_t a, uint64_t b) {
    uint64_t r; asm("mul.rn.f32x2 %0, %1, %2;" : "=l"(r) : "l"(a), "l"(b)); return r;
}
__device__ __forceinline__ uint64_t f2_fma(uint64_t a, uint64_t b, uint64_t c) {
    uint64_t r; asm("fma.rn.f32x2 %0, %1, %2, %3;" : "=l"(r) : "l"(a), "l"(b), "l"(c)); return r;
}
__device__ __forceinline__ uint64_t f2_pack(float lo, float hi) {
    uint64_t r; asm("mov.b64 %0, {%1, %2};" : "=l"(r) : "f"(lo), "f"(hi)); return r;
}
__device__ __forceinline__ uint64_t f2_bcast(float v) {
    uint64_t r; asm("mov.b64 %0, {%1, %1};" : "=l"(r) : "f"(v)); return r;
}
__device__ __forceinline__ void f2_unpack(float& lo, float& hi, uint64_t v) {
    asm("mov.b64 {%0, %1}, %2;" : "=f"(lo), "=f"(hi) : "l"(v));
}

__global__ void zero_out_kernel(float* out, int n) {
    int idx = blockIdx.x * blockDim.x + threadIdx.x;
    if (idx < n) out[idx] = 0.0f;
}

__global__ __launch_bounds__(BLOCK, 8)
void nbody_kernel(const float* __restrict__ pos,
                  const float* __restrict__ mass,
                  float* __restrict__ out) {
    const int tid = threadIdx.x;
    const int i0  = blockIdx.x * IBLK + tid;        // first i-body
    const int i1  = i0 + BLOCK;                     // second i-body (coalesced)

    // SoA shared tiles: each float2 holds j-bodies (2k, 2k+1) -> pre-packed f32x2
    __shared__ float2 shx[NPAIRS];
    __shared__ float2 shy[NPAIRS];
    __shared__ float2 shz[NPAIRS];
    __shared__ float2 shm[NPAIRS];

    {
        const int j = blockIdx.y * JCHUNK + 2 * tid;    // tid < 128 == NPAIRS
        shx[tid] = make_float2(pos[3 * j + 0], pos[3 * j + 3]);
        shy[tid] = make_float2(pos[3 * j + 1], pos[3 * j + 4]);
        shz[tid] = make_float2(pos[3 * j + 2], pos[3 * j + 5]);
        shm[tid] = make_float2(mass[j], mass[j + 1]);
    }

    // Broadcast-packed negated positions of the two i-bodies
    const uint64_t nx0 = f2_bcast(-pos[3 * i0 + 0]);
    const uint64_t ny0 = f2_bcast(-pos[3 * i0 + 1]);
    const uint64_t nz0 = f2_bcast(-pos[3 * i0 + 2]);
    const uint64_t nx1 = f2_bcast(-pos[3 * i1 + 0]);
    const uint64_t ny1 = f2_bcast(-pos[3 * i1 + 1]);
    const uint64_t nz1 = f2_bcast(-pos[3 * i1 + 2]);
    const uint64_t s2p = f2_bcast(SOFT2);

    __syncthreads();

    uint64_t ax0 = 0ull, ay0 = 0ull, az0 = 0ull;
    uint64_t ax1 = 0ull, ay1 = 0ull, az1 = 0ull;

    const uint64_t* __restrict__ px = reinterpret_cast<const uint64_t*>(shx);
    const uint64_t* __restrict__ py = reinterpret_cast<const uint64_t*>(shy);
    const uint64_t* __restrict__ pz = reinterpret_cast<const uint64_t*>(shz);
    const uint64_t* __restrict__ pm = reinterpret_cast<const uint64_t*>(shm);

    #pragma unroll 4
    for (int k = 0; k < NPAIRS; k++) {
        const uint64_t xp = px[k];   // LDS.64, warp-broadcast
        const uint64_t yp = py[k];
        const uint64_t zp = pz[k];
        const uint64_t mp = pm[k];

        // ---- chain 0 (i0 vs j-pair) ----
        const uint64_t dx0 = f2_add(xp, nx0);
        const uint64_t dy0 = f2_add(yp, ny0);
        const uint64_t dz0 = f2_add(zp, nz0);
        uint64_t d20 = s2p;
        d20 = f2_fma(dx0, dx0, d20);
        d20 = f2_fma(dy0, dy0, d20);
        d20 = f2_fma(dz0, dz0, d20);

        // ---- chain 1 (i1 vs j-pair) ----
        const uint64_t dx1 = f2_add(xp, nx1);
        const uint64_t dy1 = f2_add(yp, ny1);
        const uint64_t dz1 = f2_add(zp, nz1);
        uint64_t d21 = s2p;
        d21 = f2_fma(dx1, dx1, d21);
        d21 = f2_fma(dy1, dy1, d21);
        d21 = f2_fma(dz1, dz1, d21);

        float a0, b0, a1, b1;
        f2_unpack(a0, b0, d20);
        f2_unpack(a1, b1, d21);
        const uint64_t inv0 = f2_pack(rsqrtf(a0), rsqrtf(b0));
        const uint64_t inv1 = f2_pack(rsqrtf(a1), rsqrtf(b1));

        const uint64_t w0 = f2_mul(mp, f2_mul(f2_mul(inv0, inv0), inv0));
        ax0 = f2_fma(w0, dx0, ax0);
        ay0 = f2_fma(w0, dy0, ay0);
        az0 = f2_fma(w0, dz0, az0);

        const uint64_t w1 = f2_mul(mp, f2_mul(f2_mul(inv1, inv1), inv1));
        ax1 = f2_fma(w1, dx1, ax1);
        ay1 = f2_fma(w1, dy1, ay1);
        az1 = f2_fma(w1, dz1, az1);
    }

    float lo, hi;
    f2_unpack(lo, hi, ax0); atomicAdd(&out[3 * i0 + 0], lo + hi);
    f2_unpack(lo, hi, ay0); atomicAdd(&out[3 * i0 + 1], lo + hi);
    f2_unpack(lo, hi, az0); atomicAdd(&out[3 * i0 + 2], lo + hi);
    f2_unpack(lo, hi, ax1); atomicAdd(&out[3 * i1 + 0], lo + hi);
    f2_unpack(lo, hi, ay1); atomicAdd(&out[3 * i1 + 1], lo + hi);
    f2_unpack(lo, hi, az1); atomicAdd(&out[3 * i1 + 2], lo + hi);
}

extern "C" void kernel_launch(void* const* d_in, const int* in_sizes, int n_in,
                              void* d_out, int out_size) {
    const float* pos  = (const float*)d_in[0];   // (8192, 3) float32
    const float* mass = (const float*)d_in[1];   // (8192,)   float32
    float* out        = (float*)d_out;           // (8192, 3) float32

    zero_out_kernel<<<(NBODY * 3 + 255) / 256, 256>>>(out, NBODY * 3);

    dim3 grid(NBODY / IBLK, NSPLIT);              // 32 x 32 = 1024 blocks
    nbody_kernel<<<grid, BLOCK>>>(pos, mass, out);
}